// round 1
// baseline (speedup 1.0000x reference)
#include <cuda_runtime.h>
#include <math.h>

#define FF    128
#define F3    384
#define NRBF  20
#define AMAX  50000
#define PI_F  3.14159265358979323846f
#define RCUT  5.0f

// node MLP output scratch: s = silu(scalars@W1+b1)@W2+b2, [A, 384]
__device__ float g_sbuf[AMAX * F3];

// ---------------------------------------------------------------------------
__global__ void zero_kernel(float* __restrict__ out, int n) {
    int i = blockIdx.x * blockDim.x + threadIdx.x;
    if (i < n) out[i] = 0.0f;
}

// ---------------------------------------------------------------------------
// Node MLP: 32 rows per block, 256 threads.
// Phase1: h = silu(x @ W1 + b1)   (F -> F)
// Phase2: s = h @ W2 + b2         (F -> 3F), written to g_sbuf
__global__ __launch_bounds__(256) void mlp_kernel(
    const float* __restrict__ scalars, const float* __restrict__ W1,
    const float* __restrict__ b1, const float* __restrict__ W2,
    const float* __restrict__ b2, int A)
{
    __shared__ float sx[32][FF];
    __shared__ float sh[32][FF];
    const int row0 = blockIdx.x * 32;
    const int tid  = threadIdx.x;

    // load scalars tile (zero-pad tail rows)
    for (int idx = tid; idx < 32 * 32; idx += 256) {
        int m = idx >> 5, c = idx & 31;
        float4 v = make_float4(0.f, 0.f, 0.f, 0.f);
        if (row0 + m < A)
            v = reinterpret_cast<const float4*>(scalars)[(size_t)(row0 + m) * 32 + c];
        *reinterpret_cast<float4*>(&sx[m][c * 4]) = v;
    }
    __syncthreads();

    const int n  = tid & 127;
    const int m0 = (tid >> 7) * 16;

    // ---- phase 1 ----
    float acc[16];
#pragma unroll
    for (int i = 0; i < 16; i++) acc[i] = 0.f;

    for (int k = 0; k < FF; k += 4) {
        float w0 = W1[(k + 0) * FF + n];
        float w1 = W1[(k + 1) * FF + n];
        float w2 = W1[(k + 2) * FF + n];
        float w3 = W1[(k + 3) * FF + n];
#pragma unroll
        for (int i = 0; i < 16; i++) {
            float4 x4 = *reinterpret_cast<const float4*>(&sx[m0 + i][k]);
            acc[i] += x4.x * w0 + x4.y * w1 + x4.z * w2 + x4.w * w3;
        }
    }
    {
        float bb = b1[n];
#pragma unroll
        for (int i = 0; i < 16; i++) {
            float x = acc[i] + bb;
            sh[m0 + i][n] = x / (1.f + __expf(-x));
        }
    }
    __syncthreads();

    // ---- phase 2 ----
    float a2[16][3];
#pragma unroll
    for (int i = 0; i < 16; i++)
#pragma unroll
        for (int c = 0; c < 3; c++) a2[i][c] = 0.f;

    for (int k = 0; k < FF; k += 4) {
        float w[4][3];
#pragma unroll
        for (int kk = 0; kk < 4; kk++) {
            w[kk][0] = W2[(k + kk) * F3 + n];
            w[kk][1] = W2[(k + kk) * F3 + n + 128];
            w[kk][2] = W2[(k + kk) * F3 + n + 256];
        }
#pragma unroll
        for (int i = 0; i < 16; i++) {
            float4 h4 = *reinterpret_cast<const float4*>(&sh[m0 + i][k]);
            a2[i][0] += h4.x * w[0][0] + h4.y * w[1][0] + h4.z * w[2][0] + h4.w * w[3][0];
            a2[i][1] += h4.x * w[0][1] + h4.y * w[1][1] + h4.z * w[2][1] + h4.w * w[3][1];
            a2[i][2] += h4.x * w[0][2] + h4.y * w[1][2] + h4.z * w[2][2] + h4.w * w[3][2];
        }
    }
    {
        float c0 = b2[n], c1 = b2[n + 128], c2v = b2[n + 256];
#pragma unroll
        for (int i = 0; i < 16; i++) {
            int row = row0 + m0 + i;
            if (row < A) {
                g_sbuf[(size_t)row * F3 + n]       = a2[i][0] + c0;
                g_sbuf[(size_t)row * F3 + n + 128] = a2[i][1] + c1;
                g_sbuf[(size_t)row * F3 + n + 256] = a2[i][2] + c2v;
            }
        }
    }
}

// ---------------------------------------------------------------------------
__device__ __forceinline__ void red4(float* p, float4 v) {
    asm volatile("red.global.add.v4.f32 [%0], {%1, %2, %3, %4};"
                 :: "l"(p), "f"(v.x), "f"(v.y), "f"(v.z), "f"(v.w)
                 : "memory");
}

// Edge kernel: 8 warps/block, 2 edges per warp (Wr smem loads amortized over
// both edges). Lane owns 4 feature channels (f = lane*4 .. lane*4+3) in each
// of the 3 output groups (delta_s, delta_v1, delta_v2).
__global__ __launch_bounds__(256) void edge_kernel(
    const float* __restrict__ vectors, const float* __restrict__ directions,
    const int* __restrict__ idx_i, const int* __restrict__ idx_j,
    const float* __restrict__ Wr, const float* __restrict__ br,
    float* __restrict__ out_v, float* __restrict__ out_s, int E)
{
    __shared__ float4 swr[NRBF * 96];   // Wr [20][384] as float4
    __shared__ float  sbr[F3];

    const int tid = threadIdx.x;
    for (int i2 = tid; i2 < NRBF * 96; i2 += 256)
        swr[i2] = reinterpret_cast<const float4*>(Wr)[i2];
    for (int i2 = tid; i2 < F3; i2 += 256) sbr[i2] = br[i2];
    __syncthreads();

    const int warp = tid >> 5;
    const int lane = tid & 31;
    const int ebase = (blockIdx.x * 8 + warp) * 2;

    float d0[2], d1[2], d2[2], inv[2], fc[2], scale[2], c2r[2], scur[2], sprev[2];
    int   ii[2], jj[2];
    bool  val[2];

#pragma unroll
    for (int e = 0; e < 2; e++) {
        int ee = ebase + e;
        val[e] = (ee < E);
        d0[e] = 0.f; d1[e] = 0.f; d2[e] = 0.f; ii[e] = 0; jj[e] = 0;
        if (val[e]) {
            d0[e] = directions[(size_t)ee * 3 + 0];
            d1[e] = directions[(size_t)ee * 3 + 1];
            d2[e] = directions[(size_t)ee * 3 + 2];
            ii[e] = idx_i[ee];
            jj[e] = idx_j[ee];
        }
        float nrm = sqrtf(d0[e] * d0[e] + d1[e] * d1[e] + d2[e] * d2[e]);
        inv[e] = 1.f / nrm;
        float x = (PI_F / RCUT) * nrm;
        float s1, c1;
        sincosf(x, &s1, &c1);
        c2r[e]  = 2.f * c1;
        scur[e] = s1;          // sin(1*x)
        sprev[e] = 0.f;        // sin(0*x)
        float delta = nrm - RCUT;
        float mask  = fminf(delta, 0.f) / delta;     // 1 inside, 0 outside, NaN at ==
        fc[e]    = 0.5f * (c1 + 1.f) * mask;
        scale[e] = fc[e] * inv[e];                   // applies the 1/|r| of rbf
    }

    // accumulate sum_k sin(k*x) * Wr[k][group, 4 channels]
    float4 aA[2], aB[2], aC[2];
#pragma unroll
    for (int e = 0; e < 2; e++) {
        aA[e] = make_float4(0.f, 0.f, 0.f, 0.f);
        aB[e] = make_float4(0.f, 0.f, 0.f, 0.f);
        aC[e] = make_float4(0.f, 0.f, 0.f, 0.f);
    }

#pragma unroll
    for (int k = 0; k < NRBF; k++) {
        float4 wA = swr[k * 96 + lane];
        float4 wB = swr[k * 96 + 32 + lane];
        float4 wC = swr[k * 96 + 64 + lane];
#pragma unroll
        for (int e = 0; e < 2; e++) {
            float s = scur[e];
            aA[e].x += wA.x * s; aA[e].y += wA.y * s; aA[e].z += wA.z * s; aA[e].w += wA.w * s;
            aB[e].x += wB.x * s; aB[e].y += wB.y * s; aB[e].z += wB.z * s; aB[e].w += wB.w * s;
            aC[e].x += wC.x * s; aC[e].y += wC.y * s; aC[e].z += wC.z * s; aC[e].w += wC.w * s;
            float t = c2r[e] * s - sprev[e];
            sprev[e] = s;
            scur[e]  = t;
        }
    }

    const int f4 = lane * 4;
    float4 brA = *reinterpret_cast<const float4*>(&sbr[f4]);
    float4 brB = *reinterpret_cast<const float4*>(&sbr[128 + f4]);
    float4 brC = *reinterpret_cast<const float4*>(&sbr[256 + f4]);

#pragma unroll
    for (int e = 0; e < 2; e++) {
        if (!val[e]) continue;
        float sc = scale[e], f = fc[e];
        float4 rA, rB, rC;
        rA.x = sc * aA[e].x + f * brA.x; rA.y = sc * aA[e].y + f * brA.y;
        rA.z = sc * aA[e].z + f * brA.z; rA.w = sc * aA[e].w + f * brA.w;
        rB.x = sc * aB[e].x + f * brB.x; rB.y = sc * aB[e].y + f * brB.y;
        rB.z = sc * aB[e].z + f * brB.z; rB.w = sc * aB[e].w + f * brB.w;
        rC.x = sc * aC[e].x + f * brC.x; rC.y = sc * aC[e].y + f * brC.y;
        rC.z = sc * aC[e].z + f * brC.z; rC.w = sc * aC[e].w + f * brC.w;

        size_t ib = (size_t)ii[e] * F3 + f4;
        float4 sA = *reinterpret_cast<const float4*>(&g_sbuf[ib]);
        float4 sB = *reinterpret_cast<const float4*>(&g_sbuf[ib + 128]);
        float4 sC = *reinterpret_cast<const float4*>(&g_sbuf[ib + 256]);

        float4 ds, dv1, dv2;
        ds.x  = sA.x * rA.x; ds.y  = sA.y * rA.y; ds.z  = sA.z * rA.z; ds.w  = sA.w * rA.w;
        dv1.x = sB.x * rB.x; dv1.y = sB.y * rB.y; dv1.z = sB.z * rB.z; dv1.w = sB.w * rB.w;
        dv2.x = sC.x * rC.x; dv2.y = sC.y * rC.y; dv2.z = sC.z * rC.z; dv2.w = sC.w * rC.w;

        red4(out_s + (size_t)jj[e] * FF + f4, ds);

        float dh[3];
        dh[0] = d0[e] * inv[e]; dh[1] = d1[e] * inv[e]; dh[2] = d2[e] * inv[e];

        size_t vb = (size_t)ii[e] * F3 + f4;
        size_t ob = (size_t)jj[e] * F3 + f4;
#pragma unroll
        for (int d = 0; d < 3; d++) {
            float4 vv = *reinterpret_cast<const float4*>(&vectors[vb + d * 128]);
            float4 ct;
            ct.x = vv.x * dv1.x + dv2.x * dh[d];
            ct.y = vv.y * dv1.y + dv2.y * dh[d];
            ct.z = vv.z * dv1.z + dv2.z * dh[d];
            ct.w = vv.w * dv1.w + dv2.w * dh[d];
            red4(out_v + ob + d * 128, ct);
        }
    }
}

// ---------------------------------------------------------------------------
extern "C" void kernel_launch(void* const* d_in, const int* in_sizes, int n_in,
                              void* d_out, int out_size) {
    const float* vectors    = (const float*)d_in[0];
    const float* scalars    = (const float*)d_in[1];
    const float* directions = (const float*)d_in[2];
    const int*   idx_i      = (const int*)d_in[3];
    const int*   idx_j      = (const int*)d_in[4];
    const float* W1         = (const float*)d_in[5];
    const float* b1         = (const float*)d_in[6];
    const float* W2         = (const float*)d_in[7];
    const float* b2         = (const float*)d_in[8];
    const float* Wr         = (const float*)d_in[9];
    const float* br         = (const float*)d_in[10];

    const int A = in_sizes[0] / (3 * FF);
    const int E = in_sizes[2] / 3;

    float* out   = (float*)d_out;
    float* out_v = out;                          // delta_v: A x 3 x F
    float* out_s = out + (size_t)A * 3 * FF;     // delta_s: A x 1 x F

    zero_kernel<<<(out_size + 255) / 256, 256>>>(out, out_size);
    mlp_kernel<<<(A + 31) / 32, 256>>>(scalars, W1, b1, W2, b2, A);
    edge_kernel<<<(E + 15) / 16, 256>>>(vectors, directions, idx_i, idx_j,
                                        Wr, br, out_v, out_s, E);
}

// round 2
// speedup vs baseline: 1.0096x; 1.0096x over previous
#include <cuda_runtime.h>
#include <math.h>

#define FF    128
#define F3    384
#define NRBF  20
#define AMAX  50000
#define PI_F  3.14159265358979323846f
#define RCUT  5.0f

typedef unsigned long long u64;

// node MLP output scratch: s = silu(scalars@W1+b1)@W2+b2, [A, 384]
__device__ float g_sbuf[AMAX * F3];

// ---- packed fp32x2 helpers (Blackwell FFMA2 via PTX) ----------------------
__device__ __forceinline__ u64 pk2(float lo, float hi) {
    u64 r; asm("mov.b64 %0, {%1, %2};" : "=l"(r) : "f"(lo), "f"(hi)); return r;
}
__device__ __forceinline__ u64 fma2(u64 a, u64 b, u64 c) {
    u64 d; asm("fma.rn.f32x2 %0, %1, %2, %3;" : "=l"(d) : "l"(a), "l"(b), "l"(c));
    return d;
}
__device__ __forceinline__ float2 upk2(u64 v) {
    float2 f; asm("mov.b64 {%0, %1}, %2;" : "=f"(f.x), "=f"(f.y) : "l"(v)); return f;
}

// ---------------------------------------------------------------------------
// Node MLP: 32 rows per block, 256 threads, FFMA2 inner loops.
__global__ __launch_bounds__(256) void mlp_kernel(
    const float* __restrict__ scalars, const float* __restrict__ W1,
    const float* __restrict__ b1, const float* __restrict__ W2,
    const float* __restrict__ b2, int A)
{
    __shared__ float sx[32][FF];
    __shared__ float sh[32][FF];
    const int row0 = blockIdx.x * 32;
    const int tid  = threadIdx.x;

    for (int idx = tid; idx < 32 * 32; idx += 256) {
        int m = idx >> 5, c = idx & 31;
        float4 v = make_float4(0.f, 0.f, 0.f, 0.f);
        if (row0 + m < A)
            v = reinterpret_cast<const float4*>(scalars)[(size_t)(row0 + m) * 32 + c];
        *reinterpret_cast<float4*>(&sx[m][c * 4]) = v;
    }
    __syncthreads();

    const int n  = tid & 127;
    const int m0 = (tid >> 7) * 16;

    // ---- phase 1: h = silu(x @ W1 + b1) ----
    u64 acc[16];
#pragma unroll
    for (int i = 0; i < 16; i++) acc[i] = 0ull;

    for (int k = 0; k < FF; k += 4) {
        float w0 = W1[(k + 0) * FF + n];
        float w1 = W1[(k + 1) * FF + n];
        float w2 = W1[(k + 2) * FF + n];
        float w3 = W1[(k + 3) * FF + n];
        u64 wp0 = pk2(w0, w1), wp1 = pk2(w2, w3);
#pragma unroll
        for (int i = 0; i < 16; i++) {
            ulonglong2 x2 = *reinterpret_cast<const ulonglong2*>(&sx[m0 + i][k]);
            acc[i] = fma2(x2.x, wp0, acc[i]);
            acc[i] = fma2(x2.y, wp1, acc[i]);
        }
    }
    {
        float bb = b1[n];
#pragma unroll
        for (int i = 0; i < 16; i++) {
            float2 p = upk2(acc[i]);
            float x = p.x + p.y + bb;
            sh[m0 + i][n] = x / (1.f + __expf(-x));
        }
    }
    __syncthreads();

    // ---- phase 2: s = h @ W2 + b2 ----
    u64 a2[16][3];
#pragma unroll
    for (int i = 0; i < 16; i++)
#pragma unroll
        for (int c = 0; c < 3; c++) a2[i][c] = 0ull;

    for (int k = 0; k < FF; k += 4) {
        u64 wp[3][2];
#pragma unroll
        for (int c = 0; c < 3; c++) {
            float v0 = W2[(k + 0) * F3 + n + c * 128];
            float v1 = W2[(k + 1) * F3 + n + c * 128];
            float v2 = W2[(k + 2) * F3 + n + c * 128];
            float v3 = W2[(k + 3) * F3 + n + c * 128];
            wp[c][0] = pk2(v0, v1);
            wp[c][1] = pk2(v2, v3);
        }
#pragma unroll
        for (int i = 0; i < 16; i++) {
            ulonglong2 h2 = *reinterpret_cast<const ulonglong2*>(&sh[m0 + i][k]);
#pragma unroll
            for (int c = 0; c < 3; c++) {
                a2[i][c] = fma2(h2.x, wp[c][0], a2[i][c]);
                a2[i][c] = fma2(h2.y, wp[c][1], a2[i][c]);
            }
        }
    }
    {
        float c0 = b2[n], c1 = b2[n + 128], c2v = b2[n + 256];
#pragma unroll
        for (int i = 0; i < 16; i++) {
            int row = row0 + m0 + i;
            if (row < A) {
                float2 p0 = upk2(a2[i][0]);
                float2 p1 = upk2(a2[i][1]);
                float2 p2 = upk2(a2[i][2]);
                g_sbuf[(size_t)row * F3 + n]       = p0.x + p0.y + c0;
                g_sbuf[(size_t)row * F3 + n + 128] = p1.x + p1.y + c1;
                g_sbuf[(size_t)row * F3 + n + 256] = p2.x + p2.y + c2v;
            }
        }
    }
}

// ---------------------------------------------------------------------------
__device__ __forceinline__ void red4(float* p, float4 v) {
    asm volatile("red.global.add.v4.f32 [%0], {%1, %2, %3, %4};"
                 :: "l"(p), "f"(v.x), "f"(v.y), "f"(v.z), "f"(v.w)
                 : "memory");
}

#define EPW 4   // edges per warp

// Edge kernel: 8 warps/block, 4 edges/warp, FFMA2 rbf loop.
__global__ __launch_bounds__(256, 2) void edge_kernel(
    const float* __restrict__ vectors, const float* __restrict__ directions,
    const int* __restrict__ idx_i, const int* __restrict__ idx_j,
    const float* __restrict__ Wr, const float* __restrict__ br,
    float* __restrict__ out_v, float* __restrict__ out_s, int E)
{
    __shared__ float4 swr[NRBF * 96];   // Wr [20][384] as float4
    __shared__ float  sbr[F3];

    const int tid = threadIdx.x;
    for (int i2 = tid; i2 < NRBF * 96; i2 += 256)
        swr[i2] = reinterpret_cast<const float4*>(Wr)[i2];
    for (int i2 = tid; i2 < F3; i2 += 256) sbr[i2] = br[i2];
    __syncthreads();

    const int warp = tid >> 5;
    const int lane = tid & 31;
    const int ebase = (blockIdx.x * 8 + warp) * EPW;

    float d0[EPW], d1[EPW], d2[EPW], inv[EPW], fc[EPW], c2r[EPW], scur[EPW], sprev[EPW];
    int   ii[EPW], jj[EPW];
    bool  val[EPW];

#pragma unroll
    for (int e = 0; e < EPW; e++) {
        int ee = ebase + e;
        val[e] = (ee < E);
        d0[e] = 1.f; d1[e] = 0.f; d2[e] = 0.f; ii[e] = 0; jj[e] = 0;
        if (val[e]) {
            d0[e] = directions[(size_t)ee * 3 + 0];
            d1[e] = directions[(size_t)ee * 3 + 1];
            d2[e] = directions[(size_t)ee * 3 + 2];
            ii[e] = idx_i[ee];
            jj[e] = idx_j[ee];
        }
        float nrm = sqrtf(d0[e] * d0[e] + d1[e] * d1[e] + d2[e] * d2[e]);
        inv[e] = 1.f / nrm;
        float x = (PI_F / RCUT) * nrm;
        float s1, c1;
        sincosf(x, &s1, &c1);
        c2r[e]   = 2.f * c1;
        scur[e]  = s1;        // sin(1*x)
        sprev[e] = 0.f;       // sin(0*x)
        float delta = nrm - RCUT;
        float mask  = fminf(delta, 0.f) / delta;   // 1 inside, 0 outside
        fc[e] = 0.5f * (c1 + 1.f) * mask;
    }

    // accumulate sum_k sin(k*x) * Wr[k][group, 4ch] with FFMA2
    ulonglong2 aA[EPW], aB[EPW], aC[EPW];
#pragma unroll
    for (int e = 0; e < EPW; e++) {
        aA[e] = make_ulonglong2(0ull, 0ull);
        aB[e] = make_ulonglong2(0ull, 0ull);
        aC[e] = make_ulonglong2(0ull, 0ull);
    }

#pragma unroll
    for (int k = 0; k < NRBF; k++) {
        ulonglong2 wA = *reinterpret_cast<const ulonglong2*>(&swr[k * 96 + lane]);
        ulonglong2 wB = *reinterpret_cast<const ulonglong2*>(&swr[k * 96 + 32 + lane]);
        ulonglong2 wC = *reinterpret_cast<const ulonglong2*>(&swr[k * 96 + 64 + lane]);
#pragma unroll
        for (int e = 0; e < EPW; e++) {
            float s = scur[e];
            u64 sd = pk2(s, s);
            aA[e].x = fma2(wA.x, sd, aA[e].x);
            aA[e].y = fma2(wA.y, sd, aA[e].y);
            aB[e].x = fma2(wB.x, sd, aB[e].x);
            aB[e].y = fma2(wB.y, sd, aB[e].y);
            aC[e].x = fma2(wC.x, sd, aC[e].x);
            aC[e].y = fma2(wC.y, sd, aC[e].y);
            float t = c2r[e] * s - sprev[e];
            sprev[e] = s;
            scur[e]  = t;
        }
    }

    const int f4 = lane * 4;
    float4 brA = *reinterpret_cast<const float4*>(&sbr[f4]);
    float4 brB = *reinterpret_cast<const float4*>(&sbr[128 + f4]);
    float4 brC = *reinterpret_cast<const float4*>(&sbr[256 + f4]);

#pragma unroll
    for (int e = 0; e < EPW; e++) {
        if (!val[e]) continue;
        float f  = fc[e];
        float sc = f * inv[e];             // folds rbf's 1/|r|

        float2 pAx = upk2(aA[e].x), pAy = upk2(aA[e].y);
        float2 pBx = upk2(aB[e].x), pBy = upk2(aB[e].y);
        float2 pCx = upk2(aC[e].x), pCy = upk2(aC[e].y);

        float4 rA, rB, rC;
        rA.x = sc * pAx.x + f * brA.x; rA.y = sc * pAx.y + f * brA.y;
        rA.z = sc * pAy.x + f * brA.z; rA.w = sc * pAy.y + f * brA.w;
        rB.x = sc * pBx.x + f * brB.x; rB.y = sc * pBx.y + f * brB.y;
        rB.z = sc * pBy.x + f * brB.z; rB.w = sc * pBy.y + f * brB.w;
        rC.x = sc * pCx.x + f * brC.x; rC.y = sc * pCx.y + f * brC.y;
        rC.z = sc * pCy.x + f * brC.z; rC.w = sc * pCy.y + f * brC.w;

        size_t ib = (size_t)ii[e] * F3 + f4;
        float4 sA = *reinterpret_cast<const float4*>(&g_sbuf[ib]);
        float4 sB = *reinterpret_cast<const float4*>(&g_sbuf[ib + 128]);
        float4 sC = *reinterpret_cast<const float4*>(&g_sbuf[ib + 256]);

        float4 ds, dv1, dv2;
        ds.x  = sA.x * rA.x; ds.y  = sA.y * rA.y; ds.z  = sA.z * rA.z; ds.w  = sA.w * rA.w;
        dv1.x = sB.x * rB.x; dv1.y = sB.y * rB.y; dv1.z = sB.z * rB.z; dv1.w = sB.w * rB.w;
        dv2.x = sC.x * rC.x; dv2.y = sC.y * rC.y; dv2.z = sC.z * rC.z; dv2.w = sC.w * rC.w;

        red4(out_s + (size_t)jj[e] * FF + f4, ds);

        float dh0 = d0[e] * inv[e], dh1 = d1[e] * inv[e], dh2 = d2[e] * inv[e];

        size_t vb = (size_t)ii[e] * F3 + f4;
        size_t ob = (size_t)jj[e] * F3 + f4;
        float dh[3] = {dh0, dh1, dh2};
#pragma unroll
        for (int d = 0; d < 3; d++) {
            float4 vv = *reinterpret_cast<const float4*>(&vectors[vb + d * 128]);
            float4 ct;
            ct.x = vv.x * dv1.x + dv2.x * dh[d];
            ct.y = vv.y * dv1.y + dv2.y * dh[d];
            ct.z = vv.z * dv1.z + dv2.z * dh[d];
            ct.w = vv.w * dv1.w + dv2.w * dh[d];
            red4(out_v + ob + d * 128, ct);
        }
    }
}

// ---------------------------------------------------------------------------
extern "C" void kernel_launch(void* const* d_in, const int* in_sizes, int n_in,
                              void* d_out, int out_size) {
    const float* vectors    = (const float*)d_in[0];
    const float* scalars    = (const float*)d_in[1];
    const float* directions = (const float*)d_in[2];
    const int*   idx_i      = (const int*)d_in[3];
    const int*   idx_j      = (const int*)d_in[4];
    const float* W1         = (const float*)d_in[5];
    const float* b1         = (const float*)d_in[6];
    const float* W2         = (const float*)d_in[7];
    const float* b2         = (const float*)d_in[8];
    const float* Wr         = (const float*)d_in[9];
    const float* br         = (const float*)d_in[10];

    const int A = in_sizes[0] / (3 * FF);
    const int E = in_sizes[2] / 3;

    float* out   = (float*)d_out;
    float* out_v = out;                          // delta_v: A x 3 x F
    float* out_s = out + (size_t)A * 3 * FF;     // delta_s: A x 1 x F

    cudaMemsetAsync(out, 0, (size_t)out_size * sizeof(float), 0);
    mlp_kernel<<<(A + 31) / 32, 256>>>(scalars, W1, b1, W2, b2, A);
    edge_kernel<<<(E + (8 * EPW) - 1) / (8 * EPW), 256>>>(
        vectors, directions, idx_i, idx_j, Wr, br, out_v, out_s, E);
}

// round 3
// speedup vs baseline: 1.2161x; 1.2046x over previous
#include <cuda_runtime.h>
#include <math.h>

#define FF    128
#define F3    384
#define NRBF  20
#define AMAX  50000
#define EMAX  500000
#define PI_F  3.14159265358979323846f
#define RCUT  5.0f

typedef unsigned long long u64;

// scratch (device globals: allocation-free)
__device__ float g_sbuf[AMAX * F3];     // node MLP output [A,384]
__device__ int   g_cnt[AMAX];
__device__ int   g_cur[AMAX];
__device__ int   g_ii[EMAX];
__device__ int   g_jj[EMAX];
__device__ float g_dir[EMAX * 3];

// ---- packed fp32x2 helpers -------------------------------------------------
__device__ __forceinline__ u64 pk2(float lo, float hi) {
    u64 r; asm("mov.b64 %0, {%1, %2};" : "=l"(r) : "f"(lo), "f"(hi)); return r;
}
__device__ __forceinline__ u64 fma2(u64 a, u64 b, u64 c) {
    u64 d; asm("fma.rn.f32x2 %0, %1, %2, %3;" : "=l"(d) : "l"(a), "l"(b), "l"(c));
    return d;
}
__device__ __forceinline__ float2 upk2(u64 v) {
    float2 f; asm("mov.b64 {%0, %1}, %2;" : "=f"(f.x), "=f"(f.y) : "l"(v)); return f;
}

// ---------------------------------------------------------------------------
__global__ void zero_cnt_kernel(int A) {
    int i = blockIdx.x * blockDim.x + threadIdx.x;
    if (i < A) g_cnt[i] = 0;
}

__global__ void hist_kernel(const int* __restrict__ idx_i, int E) {
    int e = blockIdx.x * blockDim.x + threadIdx.x;
    if (e < E) atomicAdd(&g_cnt[idx_i[e]], 1);
}

// single-block exclusive scan over g_cnt -> g_cur (1024 threads)
__global__ __launch_bounds__(1024) void scan_kernel(int A) {
    __shared__ int wsum[32];
    __shared__ int s_carry;
    const int tid = threadIdx.x, lane = tid & 31, w = tid >> 5;
    if (tid == 0) s_carry = 0;
    __syncthreads();
    for (int base = 0; base < A; base += 1024) {
        int v = (base + tid < A) ? g_cnt[base + tid] : 0;
        int incl = v;
#pragma unroll
        for (int d = 1; d < 32; d <<= 1) {
            int t = __shfl_up_sync(0xffffffffu, incl, d);
            if (lane >= d) incl += t;
        }
        if (lane == 31) wsum[w] = incl;
        __syncthreads();
        if (w == 0) {
            int s = wsum[lane];
#pragma unroll
            for (int d = 1; d < 32; d <<= 1) {
                int t = __shfl_up_sync(0xffffffffu, s, d);
                if (lane >= d) s += t;
            }
            wsum[lane] = s;
        }
        __syncthreads();
        int blockIncl = incl + (w > 0 ? wsum[w - 1] : 0);
        int carry = s_carry;
        if (base + tid < A) g_cur[base + tid] = carry + blockIncl - v;
        __syncthreads();
        if (tid == 1023) s_carry = carry + blockIncl;
        __syncthreads();
    }
}

__global__ void scatter_kernel(const int* __restrict__ idx_i,
                               const int* __restrict__ idx_j,
                               const float* __restrict__ directions, int E) {
    int e = blockIdx.x * blockDim.x + threadIdx.x;
    if (e >= E) return;
    int i = idx_i[e];
    int pos = atomicAdd(&g_cur[i], 1);
    g_ii[pos] = i;
    g_jj[pos] = idx_j[e];
    g_dir[(size_t)pos * 3 + 0] = directions[(size_t)e * 3 + 0];
    g_dir[(size_t)pos * 3 + 1] = directions[(size_t)e * 3 + 1];
    g_dir[(size_t)pos * 3 + 2] = directions[(size_t)e * 3 + 2];
}

// ---------------------------------------------------------------------------
// Node MLP: 16 rows per block (8 per thread-half), 256 threads, FFMA2.
__global__ __launch_bounds__(256, 2) void mlp_kernel(
    const float* __restrict__ scalars, const float* __restrict__ W1,
    const float* __restrict__ b1, const float* __restrict__ W2,
    const float* __restrict__ b2, int A)
{
    __shared__ float sx[16][FF];
    __shared__ float sh[16][FF];
    const int row0 = blockIdx.x * 16;
    const int tid  = threadIdx.x;

    for (int idx = tid; idx < 16 * 32; idx += 256) {
        int m = idx >> 5, c = idx & 31;
        float4 v = make_float4(0.f, 0.f, 0.f, 0.f);
        if (row0 + m < A)
            v = reinterpret_cast<const float4*>(scalars)[(size_t)(row0 + m) * 32 + c];
        *reinterpret_cast<float4*>(&sx[m][c * 4]) = v;
    }
    __syncthreads();

    const int n  = tid & 127;
    const int m0 = (tid >> 7) * 8;

    // ---- phase 1: h = silu(x @ W1 + b1) ----
    u64 acc[8];
#pragma unroll
    for (int i = 0; i < 8; i++) acc[i] = 0ull;

    for (int k = 0; k < FF; k += 4) {
        u64 wp0 = pk2(W1[(k + 0) * FF + n], W1[(k + 1) * FF + n]);
        u64 wp1 = pk2(W1[(k + 2) * FF + n], W1[(k + 3) * FF + n]);
#pragma unroll
        for (int i = 0; i < 8; i++) {
            ulonglong2 x2 = *reinterpret_cast<const ulonglong2*>(&sx[m0 + i][k]);
            acc[i] = fma2(x2.x, wp0, acc[i]);
            acc[i] = fma2(x2.y, wp1, acc[i]);
        }
    }
    {
        float bb = b1[n];
#pragma unroll
        for (int i = 0; i < 8; i++) {
            float2 p = upk2(acc[i]);
            float x = p.x + p.y + bb;
            sh[m0 + i][n] = x / (1.f + __expf(-x));
        }
    }
    __syncthreads();

    // ---- phase 2: s = h @ W2 + b2 ----
    u64 a2[8][3];
#pragma unroll
    for (int i = 0; i < 8; i++)
#pragma unroll
        for (int c = 0; c < 3; c++) a2[i][c] = 0ull;

    for (int k = 0; k < FF; k += 4) {
        u64 wp[3][2];
#pragma unroll
        for (int c = 0; c < 3; c++) {
            wp[c][0] = pk2(W2[(k + 0) * F3 + n + c * 128], W2[(k + 1) * F3 + n + c * 128]);
            wp[c][1] = pk2(W2[(k + 2) * F3 + n + c * 128], W2[(k + 3) * F3 + n + c * 128]);
        }
#pragma unroll
        for (int i = 0; i < 8; i++) {
            ulonglong2 h2 = *reinterpret_cast<const ulonglong2*>(&sh[m0 + i][k]);
#pragma unroll
            for (int c = 0; c < 3; c++) {
                a2[i][c] = fma2(h2.x, wp[c][0], a2[i][c]);
                a2[i][c] = fma2(h2.y, wp[c][1], a2[i][c]);
            }
        }
    }
    {
        float c0 = b2[n], c1 = b2[n + 128], c2v = b2[n + 256];
#pragma unroll
        for (int i = 0; i < 8; i++) {
            int row = row0 + m0 + i;
            if (row < A) {
                float2 p0 = upk2(a2[i][0]);
                float2 p1 = upk2(a2[i][1]);
                float2 p2 = upk2(a2[i][2]);
                g_sbuf[(size_t)row * F3 + n]       = p0.x + p0.y + c0;
                g_sbuf[(size_t)row * F3 + n + 128] = p1.x + p1.y + c1;
                g_sbuf[(size_t)row * F3 + n + 256] = p2.x + p2.y + c2v;
            }
        }
    }
}

// ---------------------------------------------------------------------------
__device__ __forceinline__ void red4(float* p, float4 v) {
    asm volatile("red.global.add.v4.f32 [%0], {%1, %2, %3, %4};"
                 :: "l"(p), "f"(v.x), "f"(v.y), "f"(v.z), "f"(v.w)
                 : "memory");
}

#define EPW 4   // edges per warp

// Edge kernel over i-sorted edges: gathers are L1/L2-local.
__global__ __launch_bounds__(256, 2) void edge_kernel(
    const float* __restrict__ vectors,
    const float* __restrict__ Wr, const float* __restrict__ br,
    float* __restrict__ out_v, float* __restrict__ out_s, int E)
{
    __shared__ float4 swr[NRBF * 96];   // Wr [20][384] as float4
    __shared__ float  sbr[F3];

    const int tid = threadIdx.x;
    for (int i2 = tid; i2 < NRBF * 96; i2 += 256)
        swr[i2] = reinterpret_cast<const float4*>(Wr)[i2];
    for (int i2 = tid; i2 < F3; i2 += 256) sbr[i2] = br[i2];
    __syncthreads();

    const int warp = tid >> 5;
    const int lane = tid & 31;
    const int ebase = (blockIdx.x * 8 + warp) * EPW;

    float d0[EPW], d1[EPW], d2[EPW], inv[EPW], fc[EPW], c2r[EPW], scur[EPW], sprev[EPW];
    int   ii[EPW], jj[EPW];
    bool  val[EPW];

#pragma unroll
    for (int e = 0; e < EPW; e++) {
        int ee = ebase + e;
        val[e] = (ee < E);
        d0[e] = 1.f; d1[e] = 0.f; d2[e] = 0.f; ii[e] = 0; jj[e] = 0;
        if (val[e]) {
            d0[e] = g_dir[(size_t)ee * 3 + 0];
            d1[e] = g_dir[(size_t)ee * 3 + 1];
            d2[e] = g_dir[(size_t)ee * 3 + 2];
            ii[e] = g_ii[ee];
            jj[e] = g_jj[ee];
        }
        float nrm = sqrtf(d0[e] * d0[e] + d1[e] * d1[e] + d2[e] * d2[e]);
        inv[e] = 1.f / nrm;
        float x = (PI_F / RCUT) * nrm;
        float s1, c1;
        sincosf(x, &s1, &c1);
        c2r[e]   = 2.f * c1;
        scur[e]  = s1;
        sprev[e] = 0.f;
        float delta = nrm - RCUT;
        float mask  = fminf(delta, 0.f) / delta;
        fc[e] = 0.5f * (c1 + 1.f) * mask;
    }

    ulonglong2 aA[EPW], aB[EPW], aC[EPW];
#pragma unroll
    for (int e = 0; e < EPW; e++) {
        aA[e] = make_ulonglong2(0ull, 0ull);
        aB[e] = make_ulonglong2(0ull, 0ull);
        aC[e] = make_ulonglong2(0ull, 0ull);
    }

#pragma unroll
    for (int k = 0; k < NRBF; k++) {
        ulonglong2 wA = *reinterpret_cast<const ulonglong2*>(&swr[k * 96 + lane]);
        ulonglong2 wB = *reinterpret_cast<const ulonglong2*>(&swr[k * 96 + 32 + lane]);
        ulonglong2 wC = *reinterpret_cast<const ulonglong2*>(&swr[k * 96 + 64 + lane]);
#pragma unroll
        for (int e = 0; e < EPW; e++) {
            float s = scur[e];
            u64 sd = pk2(s, s);
            aA[e].x = fma2(wA.x, sd, aA[e].x);
            aA[e].y = fma2(wA.y, sd, aA[e].y);
            aB[e].x = fma2(wB.x, sd, aB[e].x);
            aB[e].y = fma2(wB.y, sd, aB[e].y);
            aC[e].x = fma2(wC.x, sd, aC[e].x);
            aC[e].y = fma2(wC.y, sd, aC[e].y);
            float t = c2r[e] * s - sprev[e];
            sprev[e] = s;
            scur[e]  = t;
        }
    }

    const int f4 = lane * 4;
    float4 brA = *reinterpret_cast<const float4*>(&sbr[f4]);
    float4 brB = *reinterpret_cast<const float4*>(&sbr[128 + f4]);
    float4 brC = *reinterpret_cast<const float4*>(&sbr[256 + f4]);

#pragma unroll
    for (int e = 0; e < EPW; e++) {
        if (!val[e]) continue;
        float f  = fc[e];
        float sc = f * inv[e];

        float2 pAx = upk2(aA[e].x), pAy = upk2(aA[e].y);
        float2 pBx = upk2(aB[e].x), pBy = upk2(aB[e].y);
        float2 pCx = upk2(aC[e].x), pCy = upk2(aC[e].y);

        float4 rA, rB, rC;
        rA.x = sc * pAx.x + f * brA.x; rA.y = sc * pAx.y + f * brA.y;
        rA.z = sc * pAy.x + f * brA.z; rA.w = sc * pAy.y + f * brA.w;
        rB.x = sc * pBx.x + f * brB.x; rB.y = sc * pBx.y + f * brB.y;
        rB.z = sc * pBy.x + f * brB.z; rB.w = sc * pBy.y + f * brB.w;
        rC.x = sc * pCx.x + f * brC.x; rC.y = sc * pCx.y + f * brC.y;
        rC.z = sc * pCy.x + f * brC.z; rC.w = sc * pCy.y + f * brC.w;

        size_t ib = (size_t)ii[e] * F3 + f4;
        float4 sA = *reinterpret_cast<const float4*>(&g_sbuf[ib]);
        float4 sB = *reinterpret_cast<const float4*>(&g_sbuf[ib + 128]);
        float4 sC = *reinterpret_cast<const float4*>(&g_sbuf[ib + 256]);

        float4 ds, dv1, dv2;
        ds.x  = sA.x * rA.x; ds.y  = sA.y * rA.y; ds.z  = sA.z * rA.z; ds.w  = sA.w * rA.w;
        dv1.x = sB.x * rB.x; dv1.y = sB.y * rB.y; dv1.z = sB.z * rB.z; dv1.w = sB.w * rB.w;
        dv2.x = sC.x * rC.x; dv2.y = sC.y * rC.y; dv2.z = sC.z * rC.z; dv2.w = sC.w * rC.w;

        red4(out_s + (size_t)jj[e] * FF + f4, ds);

        float dh[3];
        dh[0] = d0[e] * inv[e]; dh[1] = d1[e] * inv[e]; dh[2] = d2[e] * inv[e];

        size_t vb = (size_t)ii[e] * F3 + f4;
        size_t ob = (size_t)jj[e] * F3 + f4;
#pragma unroll
        for (int d = 0; d < 3; d++) {
            float4 vv = *reinterpret_cast<const float4*>(&vectors[vb + d * 128]);
            float4 ct;
            ct.x = vv.x * dv1.x + dv2.x * dh[d];
            ct.y = vv.y * dv1.y + dv2.y * dh[d];
            ct.z = vv.z * dv1.z + dv2.z * dh[d];
            ct.w = vv.w * dv1.w + dv2.w * dh[d];
            red4(out_v + ob + d * 128, ct);
        }
    }
}

// ---------------------------------------------------------------------------
extern "C" void kernel_launch(void* const* d_in, const int* in_sizes, int n_in,
                              void* d_out, int out_size) {
    const float* vectors    = (const float*)d_in[0];
    const float* scalars    = (const float*)d_in[1];
    const float* directions = (const float*)d_in[2];
    const int*   idx_i      = (const int*)d_in[3];
    const int*   idx_j      = (const int*)d_in[4];
    const float* W1         = (const float*)d_in[5];
    const float* b1         = (const float*)d_in[6];
    const float* W2         = (const float*)d_in[7];
    const float* b2         = (const float*)d_in[8];
    const float* Wr         = (const float*)d_in[9];
    const float* br         = (const float*)d_in[10];

    const int A = in_sizes[0] / (3 * FF);
    const int E = in_sizes[2] / 3;

    float* out   = (float*)d_out;
    float* out_v = out;                          // delta_v: A x 3 x F
    float* out_s = out + (size_t)A * 3 * FF;     // delta_s: A x 1 x F

    cudaMemsetAsync(out, 0, (size_t)out_size * sizeof(float), 0);

    // counting sort of edges by idx_i
    zero_cnt_kernel<<<(A + 255) / 256, 256>>>(A);
    hist_kernel<<<(E + 255) / 256, 256>>>(idx_i, E);
    scan_kernel<<<1, 1024>>>(A);
    scatter_kernel<<<(E + 255) / 256, 256>>>(idx_i, idx_j, directions, E);

    mlp_kernel<<<(A + 15) / 16, 256>>>(scalars, W1, b1, W2, b2, A);
    edge_kernel<<<(E + (8 * EPW) - 1) / (8 * EPW), 256>>>(
        vectors, Wr, br, out_v, out_s, E);
}